// round 6
// baseline (speedup 1.0000x reference)
#include <cuda_runtime.h>
#include <math.h>

#define CHUNKS   16
#define RES_DIM  8192
#define THREADS  512
#define BLOCKS_PER_CHUNK 27   // 432 blocks ~= one wave at 3 blocks/SM (64KB smem each)

// ---------------------------------------------------------------------------
// Kernel 0: out = proj_vars (d_out doubles as the global spmv accumulator)
// ---------------------------------------------------------------------------
__global__ void init_kernel(const float* __restrict__ proj, float* __restrict__ out, int n) {
    int i = blockIdx.x * blockDim.x + threadIdx.x;
    if (i < n) out[i] = proj[i];
}

// ---------------------------------------------------------------------------
// Kernel 1: per-chunk COO SpMV with smem accumulation, LDG.128 triple streams.
// ---------------------------------------------------------------------------
__global__ __launch_bounds__(THREADS)
void spmv_kernel(const float* __restrict__ vals,
                 const int*   __restrict__ rows,
                 const int*   __restrict__ cols,
                 const float* __restrict__ state,
                 float*       __restrict__ out,
                 int nse) {
    extern __shared__ float smem[];
    float* acc = smem;            // RES_DIM floats
    float* st  = smem + RES_DIM;  // RES_DIM floats

    const int c   = blockIdx.y;
    const int blk = blockIdx.x;
    const int nb  = gridDim.x;

    const float* __restrict__ st_g = state + (size_t)c * RES_DIM;
    for (int j = threadIdx.x; j < RES_DIM; j += THREADS) {
        acc[j] = 0.0f;
        st[j]  = st_g[j];
    }
    __syncthreads();

    const size_t base = (size_t)c * (size_t)nse;
    const float* __restrict__ v  = vals + base;
    const int*   __restrict__ r  = rows + base;
    const int*   __restrict__ cl = cols + base;

    // Restore 16B alignment: elements [0, pre) handled scalar by block 0.
    const int pre  = (int)((4 - (base & 3)) & 3);
    const int m    = nse - pre;
    const int n4   = m >> 2;            // full float4 groups
    const int tail = m & 3;

    if (blk == 0 && threadIdx.x < pre) {
        int i = threadIdx.x;
        atomicAdd(&acc[r[i]], v[i] * st[cl[i]]);
    }
    if (blk == nb - 1 && threadIdx.x < tail) {
        int i = pre + (n4 << 2) + threadIdx.x;
        atomicAdd(&acc[r[i]], v[i] * st[cl[i]]);
    }

    const float4* __restrict__ vv4 = (const float4*)(v + pre);
    const int4*   __restrict__ rr4 = (const int4*)  (r + pre);
    const int4*   __restrict__ cc4 = (const int4*)  (cl + pre);

    const int per  = (n4 + nb - 1) / nb;
    const int g_lo = blk * per;
    const int g_hi = min(g_lo + per, n4);

    int g = g_lo + threadIdx.x;
    // unroll-2 groups: 6 LDG.128 in flight per thread, 8 nnz per iteration
    for (; g + THREADS < g_hi; g += 2 * THREADS) {
        float4 va = vv4[g];           int4 ra = rr4[g];           int4 ca = cc4[g];
        float4 vb = vv4[g + THREADS]; int4 rb = rr4[g + THREADS]; int4 cb = cc4[g + THREADS];
        atomicAdd(&acc[ra.x], va.x * st[ca.x]);
        atomicAdd(&acc[ra.y], va.y * st[ca.y]);
        atomicAdd(&acc[ra.z], va.z * st[ca.z]);
        atomicAdd(&acc[ra.w], va.w * st[ca.w]);
        atomicAdd(&acc[rb.x], vb.x * st[cb.x]);
        atomicAdd(&acc[rb.y], vb.y * st[cb.y]);
        atomicAdd(&acc[rb.z], vb.z * st[cb.z]);
        atomicAdd(&acc[rb.w], vb.w * st[cb.w]);
    }
    for (; g < g_hi; g += THREADS) {
        float4 va = vv4[g]; int4 ra = rr4[g]; int4 ca = cc4[g];
        atomicAdd(&acc[ra.x], va.x * st[ca.x]);
        atomicAdd(&acc[ra.y], va.y * st[ca.y]);
        atomicAdd(&acc[ra.z], va.z * st[ca.z]);
        atomicAdd(&acc[ra.w], va.w * st[ca.w]);
    }
    __syncthreads();

    float* __restrict__ o = out + (size_t)c * RES_DIM;
    for (int j = threadIdx.x; j < RES_DIM; j += THREADS) {
        atomicAdd(&o[j], acc[j]);
    }
}

// ---------------------------------------------------------------------------
// Kernel 2: elementwise Horner of the tanh(BIAS + z) Taylor series (in place).
// ---------------------------------------------------------------------------
__global__ void horner_kernel(float* __restrict__ out, int n,
                              float k0, float k1, float k2,
                              float k3, float k4, float k5) {
    int i = blockIdx.x * blockDim.x + threadIdx.x;
    if (i < n) {
        float z = out[i];
        float p = k5;
        p = fmaf(z, p, k4);
        p = fmaf(z, p, k3);
        p = fmaf(z, p, k2);
        p = fmaf(z, p, k1);
        p = fmaf(z, p, k0);
        out[i] = p;
    }
}

// ---------------------------------------------------------------------------
extern "C" void kernel_launch(void* const* d_in, const int* in_sizes, int n_in,
                              void* d_out, int out_size) {
    const float* proj  = (const float*)d_in[0];
    const float* state = (const float*)d_in[1];
    const float* vals  = (const float*)d_in[2];
    const int*   rows  = (const int*)  d_in[3];
    const int*   cols  = (const int*)  d_in[4];
    float*       out   = (float*)d_out;

    const int nse = in_sizes[2] / CHUNKS;
    const int n   = out_size;  // CHUNKS * RES_DIM

    // Taylor coefficients of tanh(1.6 + z) around z=0, fp32 (matches reference)
    const float t  = tanhf(1.6f);
    const float t2 = t * t, t3 = t2 * t, t4 = t2 * t2, t6 = t4 * t2;
    const float k0 = t;
    const float k1 = 1.0f - t2;
    const float k2 = t3 - t;
    const float k3 = -t4 + (4.0f / 3.0f) * t2 - 1.0f / 3.0f;
    const float k4 = (t / 3.0f) * (3.0f * t4 - 5.0f * t2 + 2.0f);
    const float k5 = -t6 + 2.0f * t4 - (17.0f / 15.0f) * t2 + 2.0f / 15.0f;

    const int smem_bytes = 2 * RES_DIM * sizeof(float);  // 64KB
    cudaFuncSetAttribute(spmv_kernel, cudaFuncAttributeMaxDynamicSharedMemorySize, smem_bytes);

    init_kernel<<<(n + 511) / 512, 512>>>(proj, out, n);

    dim3 grid(BLOCKS_PER_CHUNK, CHUNKS);
    spmv_kernel<<<grid, THREADS, smem_bytes>>>(vals, rows, cols, state, out, nse);

    horner_kernel<<<(n + 511) / 512, 512>>>(out, n, k0, k1, k2, k3, k4, k5);
}

// round 8
// speedup vs baseline: 1.3295x; 1.3295x over previous
#include <cuda_runtime.h>
#include <math.h>

#define CHUNKS   16
#define RES_DIM  8192
#define NB       18      // blocks per chunk: 288 blocks = one wave at 2 blocks/SM
#define THREADS  1024

// ---------------------------------------------------------------------------
// Kernel 0: out = proj_vars (d_out doubles as the global spmv accumulator)
// ---------------------------------------------------------------------------
__global__ void init_kernel(const float4* __restrict__ proj, float4* __restrict__ out, int n4) {
    int i = blockIdx.x * blockDim.x + threadIdx.x;
    if (i < n4) out[i] = proj[i];
}

// ---------------------------------------------------------------------------
// Kernel 1: per-chunk COO SpMV with smem accumulation (scalar unroll-4 loads).
// ---------------------------------------------------------------------------
__global__ __launch_bounds__(THREADS)
void spmv_kernel(const float* __restrict__ vals,
                 const int*   __restrict__ rows,
                 const int*   __restrict__ cols,
                 const float* __restrict__ state,
                 float*       __restrict__ out,
                 int nse) {
    extern __shared__ float smem[];
    float* acc = smem;            // RES_DIM floats
    float* st  = smem + RES_DIM;  // RES_DIM floats

    const int c   = blockIdx.y;
    const int blk = blockIdx.x;

    const float* __restrict__ st_g = state + (size_t)c * RES_DIM;
    for (int j = threadIdx.x; j < RES_DIM; j += THREADS) {
        acc[j] = 0.0f;
        st[j]  = st_g[j];
    }
    __syncthreads();

    const size_t base = (size_t)c * (size_t)nse;
    const float* __restrict__ v  = vals + base;
    const int*   __restrict__ r  = rows + base;
    const int*   __restrict__ cl = cols + base;

    const int per = (nse + NB - 1) / NB;
    const int lo  = blk * per;
    const int hi  = min(lo + per, nse);

    int i = lo + threadIdx.x;
    // scalar unroll-4: 12 independent LDG.32 in flight before the smem work
    for (; i + 3 * THREADS < hi; i += 4 * THREADS) {
        float v0 = v[i];               int r0 = r[i];               int c0 = cl[i];
        float v1 = v[i +     THREADS]; int r1 = r[i +     THREADS]; int c1 = cl[i +     THREADS];
        float v2 = v[i + 2 * THREADS]; int r2 = r[i + 2 * THREADS]; int c2 = cl[i + 2 * THREADS];
        float v3 = v[i + 3 * THREADS]; int r3 = r[i + 3 * THREADS]; int c3 = cl[i + 3 * THREADS];
        atomicAdd(&acc[r0], v0 * st[c0]);
        atomicAdd(&acc[r1], v1 * st[c1]);
        atomicAdd(&acc[r2], v2 * st[c2]);
        atomicAdd(&acc[r3], v3 * st[c3]);
    }
    for (; i < hi; i += THREADS) {
        atomicAdd(&acc[r[i]], v[i] * st[cl[i]]);
    }
    __syncthreads();

    // Flush partials into out (seeded with proj by init_kernel).
    float* __restrict__ o = out + (size_t)c * RES_DIM;
    for (int j = threadIdx.x; j < RES_DIM; j += THREADS) {
        atomicAdd(&o[j], acc[j]);
    }
}

// ---------------------------------------------------------------------------
// Kernel 2: elementwise Horner of tanh(BIAS + z) Taylor series (in place).
// ---------------------------------------------------------------------------
__global__ void horner_kernel(float4* __restrict__ out, int n4,
                              float k0, float k1, float k2,
                              float k3, float k4, float k5) {
    int i = blockIdx.x * blockDim.x + threadIdx.x;
    if (i < n4) {
        float4 z = out[i];
        float4 res;
        {
            float p = k5;
            p = fmaf(z.x, p, k4); p = fmaf(z.x, p, k3); p = fmaf(z.x, p, k2);
            p = fmaf(z.x, p, k1); p = fmaf(z.x, p, k0); res.x = p;
        }
        {
            float p = k5;
            p = fmaf(z.y, p, k4); p = fmaf(z.y, p, k3); p = fmaf(z.y, p, k2);
            p = fmaf(z.y, p, k1); p = fmaf(z.y, p, k0); res.y = p;
        }
        {
            float p = k5;
            p = fmaf(z.z, p, k4); p = fmaf(z.z, p, k3); p = fmaf(z.z, p, k2);
            p = fmaf(z.z, p, k1); p = fmaf(z.z, p, k0); res.z = p;
        }
        {
            float p = k5;
            p = fmaf(z.w, p, k4); p = fmaf(z.w, p, k3); p = fmaf(z.w, p, k2);
            p = fmaf(z.w, p, k1); p = fmaf(z.w, p, k0); res.w = p;
        }
        out[i] = res;
    }
}

// ---------------------------------------------------------------------------
extern "C" void kernel_launch(void* const* d_in, const int* in_sizes, int n_in,
                              void* d_out, int out_size) {
    const float* proj  = (const float*)d_in[0];
    const float* state = (const float*)d_in[1];
    const float* vals  = (const float*)d_in[2];
    const int*   rows  = (const int*)  d_in[3];
    const int*   cols  = (const int*)  d_in[4];
    float*       out   = (float*)d_out;

    const int nse = in_sizes[2] / CHUNKS;
    const int n4  = out_size / 4;   // CHUNKS*RES_DIM/4, exact (8192 % 4 == 0)

    // Taylor coefficients of tanh(1.6 + z) around z=0, fp32 (matches reference)
    const float t  = tanhf(1.6f);
    const float t2 = t * t, t3 = t2 * t, t4 = t2 * t2, t6 = t4 * t2;
    const float k0 = t;
    const float k1 = 1.0f - t2;
    const float k2 = t3 - t;
    const float k3 = -t4 + (4.0f / 3.0f) * t2 - 1.0f / 3.0f;
    const float k4 = (t / 3.0f) * (3.0f * t4 - 5.0f * t2 + 2.0f);
    const float k5 = -t6 + 2.0f * t4 - (17.0f / 15.0f) * t2 + 2.0f / 15.0f;

    const int smem_bytes = 2 * RES_DIM * sizeof(float);  // 64KB
    cudaFuncSetAttribute(spmv_kernel, cudaFuncAttributeMaxDynamicSharedMemorySize, smem_bytes);

    init_kernel<<<(n4 + 511) / 512, 512>>>((const float4*)proj, (float4*)out, n4);

    dim3 grid(NB, CHUNKS);
    spmv_kernel<<<grid, THREADS, smem_bytes>>>(vals, rows, cols, state, out, nse);

    horner_kernel<<<(n4 + 511) / 512, 512>>>((float4*)out, n4, k0, k1, k2, k3, k4, k5);
}

// round 10
// speedup vs baseline: 1.3438x; 1.0107x over previous
#include <cuda_runtime.h>
#include <math.h>

#define CHUNKS   16
#define RES_DIM  8192
#define NB       18      // blocks per chunk: 288 blocks = one wave at 2 blocks/SM
#define THREADS  1024

// ---------------------------------------------------------------------------
// Kernel 0: zero d_out (write-only; d_out is the spmv atomic accumulator)
// ---------------------------------------------------------------------------
__global__ void zero_kernel(float4* __restrict__ out, int n4) {
    int i = blockIdx.x * blockDim.x + threadIdx.x;
    if (i < n4) out[i] = make_float4(0.f, 0.f, 0.f, 0.f);
}

// ---------------------------------------------------------------------------
// Kernel 1: per-chunk COO SpMV with smem accumulation (scalar unroll-4 loads).
// ---------------------------------------------------------------------------
__global__ __launch_bounds__(THREADS)
void spmv_kernel(const float* __restrict__ vals,
                 const int*   __restrict__ rows,
                 const int*   __restrict__ cols,
                 const float* __restrict__ state,
                 float*       __restrict__ out,
                 int nse) {
    extern __shared__ float smem[];
    float* acc = smem;            // RES_DIM floats
    float* st  = smem + RES_DIM;  // RES_DIM floats

    const int c   = blockIdx.y;
    const int blk = blockIdx.x;

    const float* __restrict__ st_g = state + (size_t)c * RES_DIM;
    for (int j = threadIdx.x; j < RES_DIM; j += THREADS) {
        acc[j] = 0.0f;
        st[j]  = st_g[j];
    }
    __syncthreads();

    const size_t base = (size_t)c * (size_t)nse;
    const float* __restrict__ v  = vals + base;
    const int*   __restrict__ r  = rows + base;
    const int*   __restrict__ cl = cols + base;

    const int per = (nse + NB - 1) / NB;
    const int lo  = blk * per;
    const int hi  = min(lo + per, nse);

    int i = lo + threadIdx.x;
    // scalar unroll-4: 12 independent LDG.32 in flight before the smem work
    for (; i + 3 * THREADS < hi; i += 4 * THREADS) {
        float v0 = v[i];               int r0 = r[i];               int c0 = cl[i];
        float v1 = v[i +     THREADS]; int r1 = r[i +     THREADS]; int c1 = cl[i +     THREADS];
        float v2 = v[i + 2 * THREADS]; int r2 = r[i + 2 * THREADS]; int c2 = cl[i + 2 * THREADS];
        float v3 = v[i + 3 * THREADS]; int r3 = r[i + 3 * THREADS]; int c3 = cl[i + 3 * THREADS];
        atomicAdd(&acc[r0], v0 * st[c0]);
        atomicAdd(&acc[r1], v1 * st[c1]);
        atomicAdd(&acc[r2], v2 * st[c2]);
        atomicAdd(&acc[r3], v3 * st[c3]);
    }
    for (; i < hi; i += THREADS) {
        atomicAdd(&acc[r[i]], v[i] * st[cl[i]]);
    }
    __syncthreads();

    // Flush partials into out (zero-seeded by zero_kernel).
    float* __restrict__ o = out + (size_t)c * RES_DIM;
    for (int j = threadIdx.x; j < RES_DIM; j += THREADS) {
        atomicAdd(&o[j], acc[j]);
    }
}

// ---------------------------------------------------------------------------
// Kernel 2: z = out + proj; out = Horner(tanh-Taylor, z). In place, float4.
// ---------------------------------------------------------------------------
__global__ void horner_kernel(float4* __restrict__ out,
                              const float4* __restrict__ proj, int n4,
                              float k0, float k1, float k2,
                              float k3, float k4, float k5) {
    int i = blockIdx.x * blockDim.x + threadIdx.x;
    if (i < n4) {
        float4 s  = out[i];
        float4 pj = proj[i];
        float4 z  = make_float4(s.x + pj.x, s.y + pj.y, s.z + pj.z, s.w + pj.w);
        float4 res;
        {
            float p = k5;
            p = fmaf(z.x, p, k4); p = fmaf(z.x, p, k3); p = fmaf(z.x, p, k2);
            p = fmaf(z.x, p, k1); p = fmaf(z.x, p, k0); res.x = p;
        }
        {
            float p = k5;
            p = fmaf(z.y, p, k4); p = fmaf(z.y, p, k3); p = fmaf(z.y, p, k2);
            p = fmaf(z.y, p, k1); p = fmaf(z.y, p, k0); res.y = p;
        }
        {
            float p = k5;
            p = fmaf(z.z, p, k4); p = fmaf(z.z, p, k3); p = fmaf(z.z, p, k2);
            p = fmaf(z.z, p, k1); p = fmaf(z.z, p, k0); res.z = p;
        }
        {
            float p = k5;
            p = fmaf(z.w, p, k4); p = fmaf(z.w, p, k3); p = fmaf(z.w, p, k2);
            p = fmaf(z.w, p, k1); p = fmaf(z.w, p, k0); res.w = p;
        }
        out[i] = res;
    }
}

// ---------------------------------------------------------------------------
extern "C" void kernel_launch(void* const* d_in, const int* in_sizes, int n_in,
                              void* d_out, int out_size) {
    const float* proj  = (const float*)d_in[0];
    const float* state = (const float*)d_in[1];
    const float* vals  = (const float*)d_in[2];
    const int*   rows  = (const int*)  d_in[3];
    const int*   cols  = (const int*)  d_in[4];
    float*       out   = (float*)d_out;

    const int nse = in_sizes[2] / CHUNKS;
    const int n4  = out_size / 4;   // CHUNKS*RES_DIM/4

    // Taylor coefficients of tanh(1.6 + z) around z=0, fp32 (matches reference)
    const float t  = tanhf(1.6f);
    const float t2 = t * t, t3 = t2 * t, t4 = t2 * t2, t6 = t4 * t2;
    const float k0 = t;
    const float k1 = 1.0f - t2;
    const float k2 = t3 - t;
    const float k3 = -t4 + (4.0f / 3.0f) * t2 - 1.0f / 3.0f;
    const float k4 = (t / 3.0f) * (3.0f * t4 - 5.0f * t2 + 2.0f);
    const float k5 = -t6 + 2.0f * t4 - (17.0f / 15.0f) * t2 + 2.0f / 15.0f;

    const int smem_bytes = 2 * RES_DIM * sizeof(float);  // 64KB
    cudaFuncSetAttribute(spmv_kernel, cudaFuncAttributeMaxDynamicSharedMemorySize, smem_bytes);

    zero_kernel<<<(n4 + 511) / 512, 512>>>((float4*)out, n4);

    dim3 grid(NB, CHUNKS);
    spmv_kernel<<<grid, THREADS, smem_bytes>>>(vals, rows, cols, state, out, nse);

    horner_kernel<<<(n4 + 511) / 512, 512>>>((float4*)out, (const float4*)proj, n4,
                                             k0, k1, k2, k3, k4, k5);
}